// round 16
// baseline (speedup 1.0000x reference)
#include <cuda_runtime.h>
#include <cstdint>

// Shapes fixed by the problem: B=4, N=M=8192, D=3, points uniform in [0,1)^3.
#define NB 4
#define ND 8192
#define TOTAL (2 * NB * ND)      // 65536 (dir,batch,point) slots
#define G 16                     // grid resolution per axis
#define NCELL (G * G * G)        // 4096 cells per (tensor,batch)
#define NTB 8                    // 2 tensors * 4 batches

// Sentinel: high word = FLT_MAX bits (NOT 0xFFFFFFFF = NaN, whose all-false
// comparisons disable pruning AND the exactness fallback -> NaN output).
#define BEST_INIT ((0x7F7FFFFFull << 32) | 0xFFFFFFFFull)

// ---------------- device scratch (no allocation allowed) ----------------
__device__ unsigned short g_cs[NTB * (NCELL + 1)];  // exclusive prefix + sentinel
__device__ float4   g_pts[NTB * ND];                // sorted (x,y,z, idx-bits)
__device__ unsigned g_keys[TOTAL];                  // nn index per (dir,b,point)
__device__ float    g_e[TOTAL];                     // exp(-1000 * nn_d2)
__device__ unsigned g_cnt[TOTAL];                   // density counts per direction

__device__ __forceinline__ int cell1d(float v) {
    int c = (int)(v * (float)G);
    return min(G - 1, max(0, c));
}

// ============================================================================
// build_k: fused histogram + scan + scatter (+ zero g_cnt FULLY, out).
// 8 blocks (one per tensor,batch) x 1024 threads; 8 points per thread at
// stride 1024 -> scalar loads are lane-coalesced (12B stride across lanes).
// ============================================================================
__global__ __launch_bounds__(1024)
void build_k(const float* __restrict__ x, const float* __restrict__ y,
             float* __restrict__ out) {
    __shared__ unsigned hist[NCELL];     // histogram -> cursors
    __shared__ unsigned warpsum[32];

    const unsigned tb = blockIdx.x;          // 0..7
    const unsigned t  = tb >> 2;             // tensor: 0=x, 1=y
    const unsigned b  = tb & 3u;
    const int tid = threadIdx.x;

    const float* src = (t ? y : x) + (size_t)b * ND * 3u;

    // zero histogram + FULL g_cnt slice (8192 entries) + out.
    // Full coverage every call is REQUIRED: graph replays reuse state.
    reinterpret_cast<uint4*>(hist)[tid] = make_uint4(0u, 0u, 0u, 0u);
    {
        uint4* cz = reinterpret_cast<uint4*>(g_cnt + tb * 8192u);
        cz[tid]        = make_uint4(0u, 0u, 0u, 0u);
        cz[tid + 1024] = make_uint4(0u, 0u, 0u, 0u);
    }
    if (tb == 0 && tid == 0) out[0] = 0.0f;
    __syncthreads();

    // ---- pass 1: coalesced scalar loads + histogram ----
    float px[8], py[8], pz[8];
    int   mycell[8];
    #pragma unroll
    for (int k = 0; k < 8; ++k) {
        unsigned p = (unsigned)tid + (unsigned)k * 1024u;
        px[k] = src[p * 3u + 0u];
        py[k] = src[p * 3u + 1u];
        pz[k] = src[p * 3u + 2u];
        int cx = cell1d(px[k]), cy = cell1d(py[k]), cz2 = cell1d(pz[k]);
        mycell[k] = (cz2 * G + cy) * G + cx;
        atomicAdd(&hist[mycell[k]], 1u);
    }
    __syncthreads();

    // ---- pass 2: exclusive scan of 4096 (4 per thread + 1024-scan) ----
    uint4 hv = reinterpret_cast<const uint4*>(hist)[tid];
    unsigned s = hv.x + hv.y + hv.z + hv.w;

    unsigned lane = (unsigned)tid & 31u, wid = (unsigned)tid >> 5;
    unsigned inc = s;
    #pragma unroll
    for (int o = 1; o < 32; o <<= 1) {
        unsigned u = __shfl_up_sync(0xFFFFFFFFu, inc, o);
        if (lane >= (unsigned)o) inc += u;
    }
    if (lane == 31u) warpsum[wid] = inc;
    __syncthreads();
    if (wid == 0) {
        unsigned w = warpsum[lane];
        unsigned wi = w;
        #pragma unroll
        for (int o = 1; o < 32; o <<= 1) {
            unsigned u = __shfl_up_sync(0xFFFFFFFFu, wi, o);
            if (lane >= (unsigned)o) wi += u;
        }
        warpsum[lane] = wi - w;              // exclusive warp offset
    }
    __syncthreads();

    unsigned off = warpsum[wid] + (inc - s); // thread-exclusive base
    unsigned e0 = off, e1 = off + hv.x, e2 = e1 + hv.y, e3 = e2 + hv.z;

    unsigned short* csOut = g_cs + (size_t)tb * (NCELL + 1);
    csOut[tid * 4 + 0] = (unsigned short)e0;
    csOut[tid * 4 + 1] = (unsigned short)e1;
    csOut[tid * 4 + 2] = (unsigned short)e2;
    csOut[tid * 4 + 3] = (unsigned short)e3;
    if (tid == 1023) csOut[NCELL] = (unsigned short)ND;

    __syncthreads();                         // hist reads done before overwrite
    // reuse hist as scatter cursors
    reinterpret_cast<uint4*>(hist)[tid] = make_uint4(e0, e1, e2, e3);
    __syncthreads();

    // ---- pass 3: scatter sorted points ----
    float4* pOut = g_pts + (size_t)tb * ND;
    #pragma unroll
    for (int k = 0; k < 8; ++k) {
        unsigned p = (unsigned)tid + (unsigned)k * 1024u;
        unsigned pos = atomicAdd(&hist[mycell[k]], 1u);
        pOut[pos] = make_float4(px[k], py[k], pz[k], __uint_as_float(p));
    }
}

// ---------------- branch-free candidate scan (packed u64 argmin) ----------------
// key = (bits(d2) << 32) | idx.  d2 >= 0 -> u64 order == (d2, idx) lexicographic,
// exact low-index tie-break. Inner loop has no data-dependent branches.
__device__ __forceinline__ void scan_run(const float4* __restrict__ pts,
                                         unsigned s, unsigned e,
                                         float qx, float qy, float qz,
                                         unsigned long long& best) {
    unsigned k = s;
    for (; k + 2 <= e; k += 2) {
        float4 c0 = pts[k];
        float4 c1 = pts[k + 1];
        float dx0 = qx - c0.x, dy0 = qy - c0.y, dz0 = qz - c0.z;
        float dx1 = qx - c1.x, dy1 = qy - c1.y, dz1 = qz - c1.z;
        float d0 = fmaf(dx0, dx0, fmaf(dy0, dy0, dz0 * dz0));
        float d1 = fmaf(dx1, dx1, fmaf(dy1, dy1, dz1 * dz1));
        unsigned long long k0 =
            ((unsigned long long)__float_as_uint(d0) << 32) | __float_as_uint(c0.w);
        unsigned long long k1 =
            ((unsigned long long)__float_as_uint(d1) << 32) | __float_as_uint(c1.w);
        best = min(best, min(k0, k1));
    }
    if (k < e) {
        float4 c = pts[k];
        float dx = qx - c.x, dy = qy - c.y, dz = qz - c.z;
        float d2 = fmaf(dx, dx, fmaf(dy, dy, dz * dz));
        unsigned long long kk =
            ((unsigned long long)__float_as_uint(d2) << 32) | __float_as_uint(c.w);
        best = min(best, kk);
    }
}

// axis distance from q to cell index c's slab [c*h,(c+1)*h]
__device__ __forceinline__ float axdist(float q, int c, float h) {
    float lo = (float)c * h, hi = lo + h;
    return fmaxf(0.0f, fmaxf(lo - q, q - hi));
}

// ============================================================================
// nn_k: exact grid NN. All 9 row-run bounds loaded up front (u16, L1-resident)
// for MLP; center row scanned first; other rows strictly pruned by min row
// distance; rare shell-expansion fallback guarantees exactness. Fused counts.
// ============================================================================
__global__ __launch_bounds__(128)
void nn_k() {
    int i = blockIdx.x * blockDim.x + threadIdx.x;        // [0, 65536)
    unsigned dirb = (unsigned)i >> 13;                     // dir*4 + b
    unsigned dir  = dirb >> 2;
    unsigned b    = dirb & 3u;
    unsigned ts   = dir;                                   // src tensor
    unsigned tt   = dir ^ 1u;                              // target tensor

    const float4*         qArr = g_pts + (size_t)(ts * 4u + b) * ND;
    const float4*         tArr = g_pts + (size_t)(tt * 4u + b) * ND;
    const unsigned short* cs   = g_cs  + (size_t)(tt * 4u + b) * (NCELL + 1);

    float4 q = qArr[(unsigned)i & (ND - 1)];
    float qx = q.x, qy = q.y, qz = q.z;
    unsigned orig = __float_as_uint(q.w);
    int cx = cell1d(qx), cy = cell1d(qy), cz = cell1d(qz);

    const float h = 1.0f / (float)G;
    unsigned long long best = BEST_INIT;    // high word = FLT_MAX (orders sanely)

    int xlo = max(cx - 1, 0), xhi = min(cx + 1, G - 1);

    // front-load all 9 row-run bounds (independent loads -> MLP)
    unsigned rs[9], re[9];
    float    rbound[9];
    #pragma unroll
    for (int zi = 0; zi < 3; ++zi) {
        int z = cz + zi - 1;
        bool zok = (unsigned)z < (unsigned)G;
        float dz = zok ? axdist(qz, z, h) : 0.0f;
        #pragma unroll
        for (int yi = 0; yi < 3; ++yi) {
            int y = cy + yi - 1;
            bool ok = zok && ((unsigned)y < (unsigned)G);
            int k = zi * 3 + yi;
            int rb = ((z & (G - 1)) * G + (y & (G - 1))) * G;  // safe index
            unsigned sS = cs[rb + xlo], sE = cs[rb + xhi + 1];
            rs[k] = ok ? sS : 0u;
            re[k] = ok ? sE : 0u;
            float dy = axdist(qy, y & (G - 1), h);
            rbound[k] = fmaf(dy, dy, dz * dz);
        }
    }

    // center row first (tight best for pruning), then the rest
    scan_run(tArr, rs[4], re[4], qx, qy, qz, best);
    #pragma unroll
    for (int k = 0; k < 9; ++k) {
        if (k == 4) continue;
        if (rbound[k] <= __uint_as_float((unsigned)(best >> 32)))
            scan_run(tArr, rs[k], re[k], qx, qy, qz, best);
    }

    // rare fallback: expand shells until unscanned cells are >= r*h away
    int r = 1;
    while (__uint_as_float((unsigned)(best >> 32)) > (float)(r * r) * h * h && r < G) {
        ++r;
        for (int dz = -r; dz <= r; ++dz) {
            int z = cz + dz;
            if ((unsigned)z >= (unsigned)G) continue;
            for (int dy = -r; dy <= r; ++dy) {
                int y = cy + dy;
                if ((unsigned)y >= (unsigned)G) continue;
                bool face = (dz == -r || dz == r || dy == -r || dy == r);
                int step = face ? 1 : 2 * r;
                for (int dx = -r; dx <= r; dx += step) {
                    int xc = cx + dx;
                    if ((unsigned)xc >= (unsigned)G) continue;
                    int cell = (z * G + y) * G + xc;
                    scan_run(tArr, cs[cell], cs[cell + 1], qx, qy, qz, best);
                }
            }
        }
    }

    unsigned bidx = (unsigned)best & (unsigned)(ND - 1);
    float    bd   = __uint_as_float((unsigned)(best >> 32));
    unsigned slot = dirb * ND + orig;
    g_keys[slot] = bidx;
    g_e[slot]    = __expf(-1000.0f * bd);                 // ALPHA = 1000
    atomicAdd(&g_cnt[dirb * ND + bidx], 1u);
}

// ============================================================================
// loss_k: 4 items/thread (vector loads), block reduce, one atomic per block
// ============================================================================
__global__ __launch_bounds__(256)
void loss_k(float* __restrict__ out) {
    __shared__ float red[256];
    int tid = threadIdx.x;
    int i4 = blockIdx.x * 256 + tid;                      // [0, 16384)

    uint4  kk = reinterpret_cast<const uint4*>(g_keys)[i4];
    float4 ee = reinterpret_cast<const float4*>(g_e)[i4];
    unsigned seg = ((unsigned)i4 * 4u) & ~(unsigned)(ND - 1);

    unsigned c0 = g_cnt[seg | (kk.x & (ND - 1))];
    unsigned c1 = g_cnt[seg | (kk.y & (ND - 1))];
    unsigned c2 = g_cnt[seg | (kk.z & (ND - 1))];
    unsigned c3 = g_cnt[seg | (kk.w & (ND - 1))];

    float v = (1.0f - ee.x / ((float)c0 + 1e-6f))
            + (1.0f - ee.y / ((float)c1 + 1e-6f))
            + (1.0f - ee.z / ((float)c2 + 1e-6f))
            + (1.0f - ee.w / ((float)c3 + 1e-6f));

    red[tid] = v;
    __syncthreads();
    #pragma unroll
    for (int s = 128; s > 32; s >>= 1) {
        if (tid < s) red[tid] += red[tid + s];
        __syncthreads();
    }
    if (tid < 32) {
        float w = red[tid] + red[tid + 32];
        #pragma unroll
        for (int o = 16; o > 0; o >>= 1)
            w += __shfl_down_sync(0xFFFFFFFFu, w, o);
        if (tid == 0)
            atomicAdd(out, w * (1.0f / (float)TOTAL));    // mean_b((l1+l2)/2)
    }
}

extern "C" void kernel_launch(void* const* d_in, const int* in_sizes, int n_in,
                              void* d_out, int out_size) {
    const float* x = (const float*)d_in[0];
    const float* y = (const float*)d_in[1];
    float* out = (float*)d_out;

    build_k<<<NTB, 1024>>>(x, y, out);
    nn_k   <<<TOTAL / 128, 128>>>();
    loss_k <<<TOTAL / 1024, 256>>>(out);
}

// round 17
// speedup vs baseline: 1.0655x; 1.0655x over previous
#include <cuda_runtime.h>
#include <cstdint>

// Shapes fixed by the problem: B=4, N=M=8192, D=3, points uniform in [0,1)^3.
#define NB 4
#define ND 8192
#define TOTAL (2 * NB * ND)      // 65536 (dir,batch,point) slots
#define G 16                     // grid resolution per axis
#define NCELL (G * G * G)        // 4096 cells per (tensor,batch)
#define NTB 8                    // 2 tensors * 4 batches

// ---------------- device scratch (no allocation allowed) ----------------
__device__ unsigned short g_cs[NTB * (NCELL + 1)];  // exclusive prefix + sentinel
__device__ float4   g_pts[NTB * ND];                // sorted (x,y,z, idx-bits)
__device__ unsigned g_keys[TOTAL];                  // nn index per (dir,b,point)
__device__ float    g_e[TOTAL];                     // exp(-1000 * nn_d2)
__device__ unsigned g_cnt[TOTAL];                   // density counts per direction

__device__ __forceinline__ int cell1d(float v) {
    int c = (int)(v * (float)G);
    return min(G - 1, max(0, c));
}

// ============================================================================
// build_k: fused histogram + scan + scatter (+ zero g_cnt FULLY, out).
// 8 blocks (one per tensor,batch) x 1024 threads; 8 points per thread at
// stride 1024 -> scalar loads are lane-coalesced (12B stride across lanes).
// ============================================================================
__global__ __launch_bounds__(1024)
void build_k(const float* __restrict__ x, const float* __restrict__ y,
             float* __restrict__ out) {
    __shared__ unsigned hist[NCELL];     // histogram -> cursors
    __shared__ unsigned warpsum[32];

    const unsigned tb = blockIdx.x;          // 0..7
    const unsigned t  = tb >> 2;             // tensor: 0=x, 1=y
    const unsigned b  = tb & 3u;
    const int tid = threadIdx.x;

    const float* src = (t ? y : x) + (size_t)b * ND * 3u;

    // zero histogram + FULL g_cnt slice (8192 entries) + out.
    // Full coverage every call is REQUIRED: graph replays reuse state.
    reinterpret_cast<uint4*>(hist)[tid] = make_uint4(0u, 0u, 0u, 0u);
    {
        uint4* cz = reinterpret_cast<uint4*>(g_cnt + tb * 8192u);
        cz[tid]        = make_uint4(0u, 0u, 0u, 0u);
        cz[tid + 1024] = make_uint4(0u, 0u, 0u, 0u);
    }
    if (tb == 0 && tid == 0) out[0] = 0.0f;
    __syncthreads();

    // ---- pass 1: coalesced scalar loads + histogram ----
    float px[8], py[8], pz[8];
    int   mycell[8];
    #pragma unroll
    for (int k = 0; k < 8; ++k) {
        unsigned p = (unsigned)tid + (unsigned)k * 1024u;
        px[k] = src[p * 3u + 0u];
        py[k] = src[p * 3u + 1u];
        pz[k] = src[p * 3u + 2u];
        int cx = cell1d(px[k]), cy = cell1d(py[k]), cz2 = cell1d(pz[k]);
        mycell[k] = (cz2 * G + cy) * G + cx;
        atomicAdd(&hist[mycell[k]], 1u);
    }
    __syncthreads();

    // ---- pass 2: exclusive scan of 4096 (4 per thread + 1024-scan) ----
    uint4 hv = reinterpret_cast<const uint4*>(hist)[tid];
    unsigned s = hv.x + hv.y + hv.z + hv.w;

    unsigned lane = (unsigned)tid & 31u, wid = (unsigned)tid >> 5;
    unsigned inc = s;
    #pragma unroll
    for (int o = 1; o < 32; o <<= 1) {
        unsigned u = __shfl_up_sync(0xFFFFFFFFu, inc, o);
        if (lane >= (unsigned)o) inc += u;
    }
    if (lane == 31u) warpsum[wid] = inc;
    __syncthreads();
    if (wid == 0) {
        unsigned w = warpsum[lane];
        unsigned wi = w;
        #pragma unroll
        for (int o = 1; o < 32; o <<= 1) {
            unsigned u = __shfl_up_sync(0xFFFFFFFFu, wi, o);
            if (lane >= (unsigned)o) wi += u;
        }
        warpsum[lane] = wi - w;              // exclusive warp offset
    }
    __syncthreads();

    unsigned off = warpsum[wid] + (inc - s); // thread-exclusive base
    unsigned e0 = off, e1 = off + hv.x, e2 = e1 + hv.y, e3 = e2 + hv.z;

    unsigned short* csOut = g_cs + (size_t)tb * (NCELL + 1);
    csOut[tid * 4 + 0] = (unsigned short)e0;
    csOut[tid * 4 + 1] = (unsigned short)e1;
    csOut[tid * 4 + 2] = (unsigned short)e2;
    csOut[tid * 4 + 3] = (unsigned short)e3;
    if (tid == 1023) csOut[NCELL] = (unsigned short)ND;

    __syncthreads();                         // hist reads done before overwrite
    // reuse hist as scatter cursors
    reinterpret_cast<uint4*>(hist)[tid] = make_uint4(e0, e1, e2, e3);
    __syncthreads();

    // ---- pass 3: scatter sorted points ----
    float4* pOut = g_pts + (size_t)tb * ND;
    #pragma unroll
    for (int k = 0; k < 8; ++k) {
        unsigned p = (unsigned)tid + (unsigned)k * 1024u;
        unsigned pos = atomicAdd(&hist[mycell[k]], 1u);
        pOut[pos] = make_float4(px[k], py[k], pz[k], __uint_as_float(p));
    }
}

// ---------------- parity candidate scan (float predicated argmin) ----------------
// Thread scans candidates k = s+par, s+par+2, ... within [s,e).
__device__ __forceinline__ void scan_run2(const float4* __restrict__ pts,
                                          unsigned s, unsigned e, unsigned par,
                                          float qx, float qy, float qz,
                                          float& best, unsigned& bidx) {
    for (unsigned k = s + par; k < e; k += 2) {
        float4 c = pts[k];
        float dx = qx - c.x, dy = qy - c.y, dz = qz - c.z;
        float d2 = fmaf(dx, dx, fmaf(dy, dy, dz * dz));
        unsigned ti = __float_as_uint(c.w);
        if (d2 < best || (d2 == best && ti < bidx)) { best = d2; bidx = ti; }
    }
}

// axis distance from q to cell index c's slab [c*h,(c+1)*h]
__device__ __forceinline__ float axdist(float q, int c, float h) {
    float lo = (float)c * h, hi = lo + h;
    return fmaxf(0.0f, fmaxf(lo - q, q - hi));
}

// ============================================================================
// nn_k: exact grid NN, TWO threads per query (lane pair, candidate parity
// split) to double latency-hiding warps. Each thread's shell-expansion rule is
// self-consistent for its parity subset -> combined min is exact. Row-run
// bounds front-loaded (u16, L1-resident); center row first; strict pruning.
// Pair results merged with one u64 shfl; even lane writes + counts.
// ============================================================================
__global__ __launch_bounds__(256)
void nn_k() {
    int tgid = blockIdx.x * blockDim.x + threadIdx.x;     // [0, 131072)
    unsigned par = (unsigned)tgid & 1u;
    unsigned i   = (unsigned)tgid >> 1;                    // query id [0, 65536)

    unsigned dirb = i >> 13;                               // dir*4 + b
    unsigned dir  = dirb >> 2;
    unsigned b    = dirb & 3u;
    unsigned ts   = dir;                                   // src tensor
    unsigned tt   = dir ^ 1u;                              // target tensor

    const float4*         qArr = g_pts + (size_t)(ts * 4u + b) * ND;
    const float4*         tArr = g_pts + (size_t)(tt * 4u + b) * ND;
    const unsigned short* cs   = g_cs  + (size_t)(tt * 4u + b) * (NCELL + 1);

    float4 q = qArr[i & (ND - 1)];
    float qx = q.x, qy = q.y, qz = q.z;
    unsigned orig = __float_as_uint(q.w);
    int cx = cell1d(qx), cy = cell1d(qy), cz = cell1d(qz);

    const float h = 1.0f / (float)G;
    float    best = 3.0e38f;
    unsigned bidx = 0xFFFFFFFFu;

    int xlo = max(cx - 1, 0), xhi = min(cx + 1, G - 1);

    // front-load all 9 row-run bounds (independent loads -> MLP)
    unsigned rs[9], re[9];
    float    rbound[9];
    #pragma unroll
    for (int zi = 0; zi < 3; ++zi) {
        int z = cz + zi - 1;
        bool zok = (unsigned)z < (unsigned)G;
        float dz = zok ? axdist(qz, z, h) : 0.0f;
        #pragma unroll
        for (int yi = 0; yi < 3; ++yi) {
            int y = cy + yi - 1;
            bool ok = zok && ((unsigned)y < (unsigned)G);
            int k = zi * 3 + yi;
            int rb = ((z & (G - 1)) * G + (y & (G - 1))) * G;  // safe index
            unsigned sS = cs[rb + xlo], sE = cs[rb + xhi + 1];
            rs[k] = ok ? sS : 0u;
            re[k] = ok ? sE : 0u;
            float dy = axdist(qy, y & (G - 1), h);
            rbound[k] = fmaf(dy, dy, dz * dz);
        }
    }

    // center row first (tight best for pruning), then the rest.
    // Pruning with this thread's own best is conservative -> exact.
    scan_run2(tArr, rs[4], re[4], par, qx, qy, qz, best, bidx);
    #pragma unroll
    for (int k = 0; k < 9; ++k) {
        if (k == 4) continue;
        if (rbound[k] <= best)
            scan_run2(tArr, rs[k], re[k], par, qx, qy, qz, best, bidx);
    }

    // rare fallback: expand shells until unscanned cells are >= r*h away
    // (per-thread rule; guarantees min over THIS parity subset -> pair-exact)
    int r = 1;
    while (best > (float)(r * r) * h * h && r < G) {
        ++r;
        for (int dz = -r; dz <= r; ++dz) {
            int z = cz + dz;
            if ((unsigned)z >= (unsigned)G) continue;
            for (int dy = -r; dy <= r; ++dy) {
                int y = cy + dy;
                if ((unsigned)y >= (unsigned)G) continue;
                bool face = (dz == -r || dz == r || dy == -r || dy == r);
                int step = face ? 1 : 2 * r;
                for (int dx = -r; dx <= r; dx += step) {
                    int xc = cx + dx;
                    if ((unsigned)xc >= (unsigned)G) continue;
                    int cell = (z * G + y) * G + xc;
                    scan_run2(tArr, cs[cell], cs[cell + 1], par, qx, qy, qz, best, bidx);
                }
            }
        }
    }

    // merge lane pair: u64 key (d2 bits << 32 | idx) -> exact (d2, idx) order
    unsigned long long key =
        ((unsigned long long)__float_as_uint(best) << 32) | bidx;
    unsigned long long other = __shfl_xor_sync(0xFFFFFFFFu, key, 1);
    key = min(key, other);

    if (par == 0u) {
        unsigned bi = (unsigned)key & (unsigned)(ND - 1);
        float    bd = __uint_as_float((unsigned)(key >> 32));
        unsigned slot = dirb * ND + orig;
        g_keys[slot] = bi;
        g_e[slot]    = __expf(-1000.0f * bd);             // ALPHA = 1000
        atomicAdd(&g_cnt[dirb * ND + bi], 1u);
    }
}

// ============================================================================
// loss_k: 4 items/thread (vector loads), block reduce, one atomic per block
// ============================================================================
__global__ __launch_bounds__(256)
void loss_k(float* __restrict__ out) {
    __shared__ float red[256];
    int tid = threadIdx.x;
    int i4 = blockIdx.x * 256 + tid;                      // [0, 16384)

    uint4  kk = reinterpret_cast<const uint4*>(g_keys)[i4];
    float4 ee = reinterpret_cast<const float4*>(g_e)[i4];
    unsigned seg = ((unsigned)i4 * 4u) & ~(unsigned)(ND - 1);

    unsigned c0 = g_cnt[seg | (kk.x & (ND - 1))];
    unsigned c1 = g_cnt[seg | (kk.y & (ND - 1))];
    unsigned c2 = g_cnt[seg | (kk.z & (ND - 1))];
    unsigned c3 = g_cnt[seg | (kk.w & (ND - 1))];

    float v = (1.0f - ee.x / ((float)c0 + 1e-6f))
            + (1.0f - ee.y / ((float)c1 + 1e-6f))
            + (1.0f - ee.z / ((float)c2 + 1e-6f))
            + (1.0f - ee.w / ((float)c3 + 1e-6f));

    red[tid] = v;
    __syncthreads();
    #pragma unroll
    for (int s = 128; s > 32; s >>= 1) {
        if (tid < s) red[tid] += red[tid + s];
        __syncthreads();
    }
    if (tid < 32) {
        float w = red[tid] + red[tid + 32];
        #pragma unroll
        for (int o = 16; o > 0; o >>= 1)
            w += __shfl_down_sync(0xFFFFFFFFu, w, o);
        if (tid == 0)
            atomicAdd(out, w * (1.0f / (float)TOTAL));    // mean_b((l1+l2)/2)
    }
}

extern "C" void kernel_launch(void* const* d_in, const int* in_sizes, int n_in,
                              void* d_out, int out_size) {
    const float* x = (const float*)d_in[0];
    const float* y = (const float*)d_in[1];
    float* out = (float*)d_out;

    build_k<<<NTB, 1024>>>(x, y, out);
    nn_k   <<<(2 * TOTAL) / 256, 256>>>();
    loss_k <<<TOTAL / 1024, 256>>>(out);
}